// round 17
// baseline (speedup 1.0000x reference)
#include <cuda_runtime.h>
#include <cstdint>

// ChamferLoss: B=4, C=3, N=M=8192
// loss = 2/B * sum_{b,n} max( min_m ||q_bn - r_bm||^2 , 0 )
//
// 16-way ref split (512 pts, 8KB smem). 512 blocks, 4 CTAs/SM -> SINGLE WAVE.
// 1024 queries/block (4 per thread) vs one 512-pt ref slice, f32x2 FMAs.
// Per-query clamped minima merged via atomicMax on INVERTED float bits:
// for v>=0, ~bits(v) is monotone decreasing, so max(~bits) == min(v) and the
// identity is 0 -> static zero-init, no init kernel. Finalize resets keys to 0.

#define BATCH     4
#define NPTS      8192
#define NSPLIT    16
#define SPTS      (NPTS / NSPLIT)     // 512 ref points per block
#define NPAIRS_B  (SPTS / 2)          // 256 pairs per block
#define TPB       256
#define QPT       4
#define QPB       (TPB * QPT)         // 1024 queries per block
#define QBLOCKS   (NPTS / QPB)        // 8
#define NBLOCKS   (BATCH * QBLOCKS * NSPLIT)  // 512
#define BN        (BATCH * NPTS)      // 32768

__device__ unsigned g_key[BN];        // zero-initialized; key = ~bits(clamped min)
__device__ int      g_count = 0;

__device__ __forceinline__ uint64_t pk2(float lo, float hi) {
    uint64_t r;
    asm("mov.b64 %0, {%1, %2};" : "=l"(r) : "f"(lo), "f"(hi));
    return r;
}
__device__ __forceinline__ uint64_t fma_f32x2(uint64_t a, uint64_t b, uint64_t c) {
    uint64_t d;
    asm("fma.rn.f32x2 %0, %1, %2, %3;" : "=l"(d) : "l"(a), "l"(b), "l"(c));
    return d;
}
__device__ __forceinline__ float2 upk2(uint64_t v) {
    float2 r;
    asm("mov.b64 {%0, %1}, %2;" : "=f"(r.x), "=f"(r.y) : "l"(v));
    return r;
}

__global__ void __launch_bounds__(TPB, 4)
chamfer_kernel(const float* __restrict__ pc2,
               const float* __restrict__ pc1w,
               float* __restrict__ out)
{
    __shared__ float4 s[2 * NPAIRS_B];   // 8 KB static

    // blockIdx.x = ((b*QBLOCKS)+qb)*NSPLIT + se
    const int se = blockIdx.x & (NSPLIT - 1);
    const int bq = blockIdx.x >> 4;
    const int b  = bq / QBLOCKS;
    const int qb = bq % QBLOCKS;

    // Stage this slice's refs, pre-scaled (-2x,-2y,-2z,|r|^2), pair-packed.
    // NPAIRS_B == TPB: exactly one pair per thread.
    {
        const float* __restrict__ rp = pc1w + (size_t)b * 3 * NPTS + se * SPTS;
        int p = threadIdx.x;
        float x0 = rp[2 * p],            x1 = rp[2 * p + 1];
        float y0 = rp[NPTS + 2 * p],     y1 = rp[NPTS + 2 * p + 1];
        float z0 = rp[2 * NPTS + 2 * p], z1 = rp[2 * NPTS + 2 * p + 1];
        float w0 = fmaf(x0, x0, fmaf(y0, y0, z0 * z0));
        float w1 = fmaf(x1, x1, fmaf(y1, y1, z1 * z1));
        s[2 * p]     = make_float4(-2.0f * x0, -2.0f * x1, -2.0f * y0, -2.0f * y1);
        s[2 * p + 1] = make_float4(-2.0f * z0, -2.0f * z1, w0, w1);
    }
    __syncthreads();

    // Four query points per thread.
    const int na = qb * QPB + threadIdx.x;
    const int nb = na + TPB;
    const int nc = na + 2 * TPB;
    const int nd = na + 3 * TPB;
    const float* __restrict__ qp = pc2 + (size_t)b * 3 * NPTS;
    const float qxa = qp[na], qya = qp[NPTS + na], qza = qp[2 * NPTS + na];
    const float qxb = qp[nb], qyb = qp[NPTS + nb], qzb = qp[2 * NPTS + nb];
    const float qxc = qp[nc], qyc = qp[NPTS + nc], qzc = qp[2 * NPTS + nc];
    const float qxd = qp[nd], qyd = qp[NPTS + nd], qzd = qp[2 * NPTS + nd];
    const float q2a = fmaf(qxa, qxa, fmaf(qya, qya, qza * qza));
    const float q2b = fmaf(qxb, qxb, fmaf(qyb, qyb, qzb * qzb));
    const float q2c = fmaf(qxc, qxc, fmaf(qyc, qyc, qzc * qzc));
    const float q2d = fmaf(qxd, qxd, fmaf(qyd, qyd, qzd * qzd));

    const uint64_t QXA = pk2(qxa, qxa), QYA = pk2(qya, qya), QZA = pk2(qza, qza);
    const uint64_t QXB = pk2(qxb, qxb), QYB = pk2(qyb, qyb), QZB = pk2(qzb, qzb);
    const uint64_t QXC = pk2(qxc, qxc), QYC = pk2(qyc, qyc), QZC = pk2(qzc, qzc);
    const uint64_t QXD = pk2(qxd, qxd), QYD = pk2(qyd, qyd), QZD = pk2(qzd, qzd);

    float ma0 = 3.4e38f, ma1 = 3.4e38f;
    float mb0 = 3.4e38f, mb1 = 3.4e38f;
    float mc0 = 3.4e38f, mc1 = 3.4e38f;
    float md0 = 3.4e38f, md1 = 3.4e38f;

    const char* sb = (const char*)s;

    #pragma unroll 1
    for (int off = 0; off < NPAIRS_B * 32; off += 2 * 32) {
        uint64_t X[2], Y[2], Z[2], W[2];
        #pragma unroll
        for (int u = 0; u < 2; u++) {
            ulonglong2 a = *(const ulonglong2*)(sb + off + u * 32);
            ulonglong2 c = *(const ulonglong2*)(sb + off + u * 32 + 16);
            X[u] = a.x; Y[u] = a.y; Z[u] = c.x; W[u] = c.y;
        }
        #pragma unroll
        for (int u = 0; u < 2; u++) {
            uint64_t za = fma_f32x2(QZA, Z[u], W[u]);
            uint64_t zb = fma_f32x2(QZB, Z[u], W[u]);
            uint64_t zc = fma_f32x2(QZC, Z[u], W[u]);
            uint64_t zd = fma_f32x2(QZD, Z[u], W[u]);
            uint64_t ta = fma_f32x2(QXA, X[u], fma_f32x2(QYA, Y[u], za));
            uint64_t tb = fma_f32x2(QXB, X[u], fma_f32x2(QYB, Y[u], zb));
            uint64_t tc = fma_f32x2(QXC, X[u], fma_f32x2(QYC, Y[u], zc));
            uint64_t td = fma_f32x2(QXD, X[u], fma_f32x2(QYD, Y[u], zd));
            float2 fa = upk2(ta), fb = upk2(tb), fc = upk2(tc), fd = upk2(td);
            ma0 = fminf(ma0, fa.x);  ma1 = fminf(ma1, fa.y);
            mb0 = fminf(mb0, fb.x);  mb1 = fminf(mb1, fb.y);
            mc0 = fminf(mc0, fc.x);  mc1 = fminf(mc1, fc.y);
            md0 = fminf(md0, fd.x);  md1 = fminf(md1, fd.y);
        }
    }

    // Clamped per-query partial; merge via atomicMax on inverted bits.
    // v >= 0  ->  ~bits(v) monotone decreasing  ->  max key == min value.
    const int base = b * NPTS;
    float va = fmaxf(q2a + fminf(ma0, ma1), 0.0f);
    float vb = fmaxf(q2b + fminf(mb0, mb1), 0.0f);
    float vc = fmaxf(q2c + fminf(mc0, mc1), 0.0f);
    float vd = fmaxf(q2d + fminf(md0, md1), 0.0f);
    atomicMax(&g_key[base + na], ~__float_as_uint(va));
    atomicMax(&g_key[base + nb], ~__float_as_uint(vb));
    atomicMax(&g_key[base + nc], ~__float_as_uint(vc));
    atomicMax(&g_key[base + nd], ~__float_as_uint(vd));

    // ---- last-block finalize (reads 128 KB, then resets keys to 0) ----
    __shared__ int is_last;
    __threadfence();
    __syncthreads();
    if (threadIdx.x == 0) {
        int old = atomicAdd(&g_count, 1);
        is_last = (old == NBLOCKS - 1);
    }
    __syncthreads();

    if (is_last) {
        __threadfence();
        uint4* g = (uint4*)g_key;
        float acc = 0.0f;
        // Fixed per-thread order -> deterministic final sum.
        for (int i = threadIdx.x; i < BN / 4; i += TPB) {
            uint4 v = g[i];
            acc += __uint_as_float(~v.x) + __uint_as_float(~v.y)
                 + __uint_as_float(~v.z) + __uint_as_float(~v.w);
            g[i] = make_uint4(0u, 0u, 0u, 0u);   // reset identity for next replay
        }
        __shared__ float red[TPB];
        red[threadIdx.x] = acc;
        __syncthreads();
        #pragma unroll
        for (int sH = TPB / 2; sH > 0; sH >>= 1) {
            if (threadIdx.x < sH) red[threadIdx.x] += red[threadIdx.x + sH];
            __syncthreads();
        }
        if (threadIdx.x == 0) {
            out[0] = red[0] * (2.0f / (float)BATCH);  // 2 * mean over batches
            g_count = 0;                               // reset for next replay
        }
    }
}

extern "C" void kernel_launch(void* const* d_in, const int* in_sizes, int n_in,
                              void* d_out, int out_size)
{
    const float* pc2  = (const float*)d_in[0];
    const float* pc1w = (const float*)d_in[1];
    float* out = (float*)d_out;

    chamfer_kernel<<<NBLOCKS, TPB>>>(pc2, pc1w, out);
}